// round 16
// baseline (speedup 1.0000x reference)
#include <cuda_runtime.h>
#include <cuda_bf16.h>
#include <cstdint>

#define T_LEN 1024
#define B_N   128
#define H_N   256
#define G3    768

typedef unsigned long long u64;

// ---------------- scratch (device globals; no allocations allowed) ----------
__device__ float g_xg[(size_t)T_LEN * B_N * G3];      // [t][b][768]
__device__ float g_seq[(size_t)B_N * T_LEN * H_N];    // [b][t][256] layer-1 output
__device__ float g_hlast[B_N * H_N];                  // layer-2 final hidden

// ---------------- helpers ---------------------------------------------------
__device__ __forceinline__ float sigmoidf_(float x) {
    return __fdividef(1.0f, 1.0f + __expf(-x));
}
__device__ __forceinline__ float tanhf_(float x) {
    float ax = fabsf(x);
    float e  = __expf(-2.0f * ax);
    float t  = __fdividef(1.0f - e, 1.0f + e);
    return copysignf(t, x);
}
__device__ __forceinline__ void cluster_arrive_() {
    asm volatile("barrier.cluster.arrive.aligned;" ::: "memory");
}
__device__ __forceinline__ void cluster_wait_() {
    asm volatile("barrier.cluster.wait.aligned;" ::: "memory");
}
__device__ __forceinline__ uint32_t smem_u32(const void* p) {
    return (uint32_t)__cvta_generic_to_shared(p);
}
__device__ __forceinline__ uint32_t mapa_(uint32_t laddr, uint32_t rank) {
    uint32_t raddr;
    asm volatile("mapa.shared::cluster.u32 %0, %1, %2;" : "=r"(raddr) : "r"(laddr), "r"(rank));
    return raddr;
}
__device__ __forceinline__ void st_remote_b16(uint32_t raddr, unsigned short v) {
    asm volatile("st.shared::cluster.b16 [%0], %1;" :: "r"(raddr), "h"(v) : "memory");
}

// ---- mma.sync / ldmatrix wrappers (sm_80-era PTX; valid on sm_100) ----
__device__ __forceinline__ void ldmx4_(uint32_t* r, uint32_t addr) {
    asm volatile("ldmatrix.sync.aligned.m8n8.x4.shared.b16 {%0,%1,%2,%3}, [%4];"
                 : "=r"(r[0]), "=r"(r[1]), "=r"(r[2]), "=r"(r[3]) : "r"(addr));
}
__device__ __forceinline__ void ldmx2_(uint32_t* r, uint32_t addr) {
    asm volatile("ldmatrix.sync.aligned.m8n8.x2.shared.b16 {%0,%1}, [%2];"
                 : "=r"(r[0]), "=r"(r[1]) : "r"(addr));
}
__device__ __forceinline__ void mma16816_(float* c, const uint32_t* a, const uint32_t* b) {
    asm volatile(
        "mma.sync.aligned.m16n8k16.row.col.f32.bf16.bf16.f32 "
        "{%0,%1,%2,%3}, {%4,%5,%6,%7}, {%8,%9}, {%0,%1,%2,%3};"
        : "+f"(c[0]), "+f"(c[1]), "+f"(c[2]), "+f"(c[3])
        : "r"(a[0]), "r"(a[1]), "r"(a[2]), "r"(a[3]), "r"(b[0]), "r"(b[1]));
}

// ============================================================================
// Input projection GEMM via mma.sync (unchanged — measured good)
// ============================================================================
#define GT_ST   264
#define OFF_BIAS 0
#define OFF_AHI  256
#define OFF_ALO  (OFF_AHI + 128 * GT_ST * 2)
#define OFF_BHI  (OFF_ALO + 128 * GT_ST * 2)
#define OFF_BLO  (OFF_BHI + 64 * GT_ST * 2)
#define GT_SMEM  (OFF_BLO + 64 * GT_ST * 2)

__global__ void __launch_bounds__(256, 1) gemm_mma_kernel(
    const float* __restrict__ Ax,
    const float* __restrict__ W,
    const float* __restrict__ bias,
    int use_gseq)
{
    extern __shared__ char smc[];
    const uint32_t sb = smem_u32(smc);
    float* sBias = (float*)(smc + OFF_BIAS);
    __nv_bfloat16* sAhi = (__nv_bfloat16*)(smc + OFF_AHI);
    __nv_bfloat16* sAlo = (__nv_bfloat16*)(smc + OFF_ALO);
    __nv_bfloat16* sBhi = (__nv_bfloat16*)(smc + OFF_BHI);
    __nv_bfloat16* sBlo = (__nv_bfloat16*)(smc + OFF_BLO);

    const float* A = use_gseq ? g_seq : Ax;

    const int tid = threadIdx.x;
    const int nt = blockIdx.x;
    const int t  = blockIdx.y;

    if (tid < 64) sBias[tid] = bias[nt * 64 + tid];

#pragma unroll
    for (int i = 0; i < 32; i++) {
        int ch  = i * 256 + tid;
        int row = ch >> 6;
        int c4  = (ch & 63) << 2;
        float4 v = *(const float4*)(A + ((size_t)row * T_LEN + t) * H_N + c4);
        __nv_bfloat16 h0 = __float2bfloat16_rn(v.x);
        __nv_bfloat16 h1 = __float2bfloat16_rn(v.y);
        __nv_bfloat16 h2 = __float2bfloat16_rn(v.z);
        __nv_bfloat16 h3 = __float2bfloat16_rn(v.w);
        __nv_bfloat16 l0 = __float2bfloat16_rn(v.x - __bfloat162float(h0));
        __nv_bfloat16 l1 = __float2bfloat16_rn(v.y - __bfloat162float(h1));
        __nv_bfloat16 l2 = __float2bfloat16_rn(v.z - __bfloat162float(h2));
        __nv_bfloat16 l3 = __float2bfloat16_rn(v.w - __bfloat162float(h3));
        int o = row * GT_ST + c4;
        *(__nv_bfloat162*)(sAhi + o)     = __nv_bfloat162(h0, h1);
        *(__nv_bfloat162*)(sAhi + o + 2) = __nv_bfloat162(h2, h3);
        *(__nv_bfloat162*)(sAlo + o)     = __nv_bfloat162(l0, l1);
        *(__nv_bfloat162*)(sAlo + o + 2) = __nv_bfloat162(l2, l3);
    }
#pragma unroll
    for (int i = 0; i < 16; i++) {
        int ch  = i * 256 + tid;
        int row = ch >> 6;
        int c4  = (ch & 63) << 2;
        float4 v = *(const float4*)(W + ((size_t)(nt * 64 + row)) * H_N + c4);
        __nv_bfloat16 h0 = __float2bfloat16_rn(v.x);
        __nv_bfloat16 h1 = __float2bfloat16_rn(v.y);
        __nv_bfloat16 h2 = __float2bfloat16_rn(v.z);
        __nv_bfloat16 h3 = __float2bfloat16_rn(v.w);
        __nv_bfloat16 l0 = __float2bfloat16_rn(v.x - __bfloat162float(h0));
        __nv_bfloat16 l1 = __float2bfloat16_rn(v.y - __bfloat162float(h1));
        __nv_bfloat16 l2 = __float2bfloat16_rn(v.z - __bfloat162float(h2));
        __nv_bfloat16 l3 = __float2bfloat16_rn(v.w - __bfloat162float(h3));
        int o = row * GT_ST + c4;
        *(__nv_bfloat162*)(sBhi + o)     = __nv_bfloat162(h0, h1);
        *(__nv_bfloat162*)(sBhi + o + 2) = __nv_bfloat162(h2, h3);
        *(__nv_bfloat162*)(sBlo + o)     = __nv_bfloat162(l0, l1);
        *(__nv_bfloat162*)(sBlo + o + 2) = __nv_bfloat162(l2, l3);
    }
    __syncthreads();

    const int wid = tid >> 5;
    const int l   = tid & 31;
    const int m0  = wid << 4;

    const uint32_t aHi = sb + OFF_AHI + ((m0 + (l & 15)) * GT_ST + ((l >> 4) << 3)) * 2;
    const uint32_t aLo = sb + OFF_ALO + ((m0 + (l & 15)) * GT_ST + ((l >> 4) << 3)) * 2;
    const uint32_t bHi = sb + OFF_BHI + (((l & 7)) * GT_ST + (((l >> 3) & 1) << 3)) * 2;
    const uint32_t bLo = sb + OFF_BLO + (((l & 7)) * GT_ST + (((l >> 3) & 1) << 3)) * 2;

    float acc[8][4];
#pragma unroll
    for (int j = 0; j < 8; j++)
#pragma unroll
        for (int i = 0; i < 4; i++) acc[j][i] = 0.0f;

#pragma unroll 2
    for (int ks = 0; ks < 16; ks++) {
        uint32_t ah[4], al[4];
        ldmx4_(ah, aHi + ks * 32);
        ldmx4_(al, aLo + ks * 32);
#pragma unroll
        for (int j = 0; j < 8; j++) {
            uint32_t bh[2], bl[2];
            ldmx2_(bh, bHi + j * (8 * GT_ST * 2) + ks * 32);
            ldmx2_(bl, bLo + j * (8 * GT_ST * 2) + ks * 32);
            mma16816_(acc[j], ah, bh);
            mma16816_(acc[j], ah, bl);
            mma16816_(acc[j], al, bh);
        }
    }

    {
        const int gp = l >> 2;
        const int tg = l & 3;
        float* dst0 = g_xg + ((size_t)t * B_N + m0 + gp) * G3 + nt * 64;
        float* dst1 = dst0 + 8 * G3;
#pragma unroll
        for (int j = 0; j < 8; j++) {
            int c = j * 8 + 2 * tg;
            float b0 = sBias[c], b1 = sBias[c + 1];
            *(float2*)(dst0 + c) = make_float2(acc[j][0] + b0, acc[j][1] + b1);
            *(float2*)(dst1 + c) = make_float2(acc[j][2] + b0, acc[j][3] + b1);
        }
    }
}

// ============================================================================
// GRU recurrence v12: R11 base (packed-N MMA, barrier.cluster sync, 256 owners
// with b16 hi/lo broadcasts — all measured-best) + K-SPLIT MMA WARPS:
//   768 threads / 24 warps; warp = (m-tile 0..11, k-half 0..1), 8 k-steps each
//   -> MMA chain depth 16 -> 8, 6 warps/SMSP for latency hiding.
// Partials staged per k-half in sHG[2][192][8]; owners sum 4 terms per gate.
// mapa bases precomputed once.
// ============================================================================
#define R_ST      264
#define ROFF_ALO  0
#define ROFF_B    (192 * R_ST * 2)                  // [2 phases][8][264] bf16
#define ROFF_HG   (ROFF_B + 2 * 8 * R_ST * 2)       // [2 kh][192][8] fp32
#define REC_SMEM  (ROFF_HG + 2 * 192 * 8 * 4)
#define B_PHASE   (8 * R_ST * 2)

__global__ void __cluster_dims__(4, 1, 1) __launch_bounds__(768, 1)
gru_rec_tc_kernel(const float* __restrict__ Whh,   // this layer's [768][256]
                  const float* __restrict__ bhh,   // this layer's [768]
                  int layer)
{
    extern __shared__ char smc[];
    const uint32_t sb = smem_u32(smc);
    __nv_bfloat16* sAlo = (__nv_bfloat16*)(smc + ROFF_ALO);
    float* sHG = (float*)(smc + ROFF_HG);

    const int tid  = threadIdx.x;               // 0..767
    const int rank = blockIdx.x & 3;
    const int b0   = (blockIdx.x >> 2) * 4;

    const int wid = tid >> 5;                   // 0..23
    const int l   = tid & 31;
    const int mt  = wid >> 1;                   // m-tile 0..11
    const int kh  = wid & 1;                    // k-half 0..1

    // ---- zero combined B buffer (both phases; h=0 -> hi=lo=0) ----
    for (int i = tid; i < (2 * B_PHASE) / 4; i += 768)
        *(uint32_t*)(smc + ROFF_B + 4 * i) = 0u;

    // ---- fill sAlo with W_hi (bf16), ldmatrix A-hi frags to regs ----
    for (int idx = tid; idx < 192 * 128; idx += 768) {
        int row = idx >> 7;
        int kp  = idx & 127;
        int jg  = ((row >> 6) << 8) + (rank << 6) + (row & 63);
        float2 v = *(const float2*)(Whh + (size_t)jg * H_N + 2 * kp);
        __nv_bfloat162 hv(__float2bfloat16_rn(v.x), __float2bfloat16_rn(v.y));
        *(__nv_bfloat162*)(sAlo + row * R_ST + 2 * kp) = hv;
    }
    __syncthreads();

    // warp's frag base (row block of its m-tile); k-step ks = kh*8 + j
    const uint32_t aBase = sb + ROFF_ALO
        + (uint32_t)((16 * mt + (l & 15)) * R_ST + ((l >> 4) << 3)) * 2;

    uint32_t ahi[8][4];
#pragma unroll
    for (int j = 0; j < 8; j++)
        ldmx4_(ahi[j], aBase + (kh * 8 + j) * 32);
    __syncthreads();

    // ---- overwrite sAlo with W_lo ----
    for (int idx = tid; idx < 192 * 128; idx += 768) {
        int row = idx >> 7;
        int kp  = idx & 127;
        int jg  = ((row >> 6) << 8) + (rank << 6) + (row & 63);
        float2 v = *(const float2*)(Whh + (size_t)jg * H_N + 2 * kp);
        __nv_bfloat16 h0 = __float2bfloat16_rn(v.x);
        __nv_bfloat16 h1 = __float2bfloat16_rn(v.y);
        __nv_bfloat162 lv(__float2bfloat16_rn(v.x - __bfloat162float(h0)),
                          __float2bfloat16_rn(v.y - __bfloat162float(h1)));
        *(__nv_bfloat162*)(sAlo + row * R_ST + 2 * kp) = lv;
    }

    // ---- owner assignment (R11 scheme): tid<256, one (unit, batch) each ----
    const int eu  = tid >> 2;                   // 0..63 (valid tid<256)
    const int eb  = tid & 3;
    const int eug = (rank << 6) + (eu & 63);
    float br_ = 0.f, bz_ = 0.f, bn_ = 0.f;
    if (tid < 256) {
        br_ = bhh[eug]; bz_ = bhh[256 + eug]; bn_ = bhh[512 + eug];
    }
    float hprev = 0.0f;

    // ---- precomputed remote store addresses (hi/lo slots, 4 ranks) ----
    uint32_t rH[4], rL[4];
    {
        uint32_t offH = (uint32_t)ROFF_B + (uint32_t)(eb * R_ST + eug) * 2;
        uint32_t offL = (uint32_t)ROFF_B + (uint32_t)((eb + 4) * R_ST + eug) * 2;
#pragma unroll
        for (uint32_t r = 0; r < 4; r++) {
            rH[r] = mapa_(sb + offH, r);
            rL[r] = mapa_(sb + offL, r);
        }
    }

    // main-loop ldmatrix bases
    const uint32_t aloB = aBase + kh * 256;     // 8 k-steps * 32B
    const uint32_t bOff = (uint32_t)((l & 7) * R_ST + (((l >> 3) & 1) << 3)) * 2
                        + (uint32_t)kh * 256;

    __syncthreads();
    cluster_arrive_();
    cluster_wait_();

    int p = 0;
    for (int t = 0; t < T_LEN; t++) {
        // ---- xg prefetch (before wait: latency hides in barrier skew) ----
        float xr = 0.f, xz = 0.f, xn = 0.f;
        if (tid < 256) {
            size_t xb = ((size_t)t * B_N + b0 + eb) * G3 + eug;
            xr = g_xg[xb]; xz = g_xg[xb + 256]; xn = g_xg[xb + 512];
        }
        if (t > 0) cluster_wait_();

        // ---- MMA phase: 8 k-steps, 2 passes over combined B ----
        const uint32_t bB = sb + ROFF_B + p * B_PHASE + bOff;
        float cH[4] = {0.f, 0.f, 0.f, 0.f};
        float cL[4] = {0.f, 0.f, 0.f, 0.f};
#pragma unroll
        for (int j = 0; j < 8; j++) {
            uint32_t bf[2], al[4];
            ldmx2_(bf, bB + j * 32);
            ldmx4_(al, aloB + j * 32);
            mma16816_(cH, ahi[j], bf);
            mma16816_(cL, al, bf);
        }
        float c0[4];
#pragma unroll
        for (int i = 0; i < 4; i++) c0[i] = cH[i] + cL[i];

        // ---- stage D frags -> sHG[kh][row][8] ----
        {
            float* hgk = sHG + kh * (192 * 8);
            int r0 = 16 * mt + (l >> 2);
            *(float2*)(hgk + r0 * 8 + 2 * (l & 3))       = make_float2(c0[0], c0[1]);
            *(float2*)(hgk + (r0 + 8) * 8 + 2 * (l & 3)) = make_float2(c0[2], c0[3]);
        }
        __syncthreads();

        // ---- elementwise: sum (2 kh) x (hi + lo cols), then gates ----
        float hnew = 0.f;
        if (tid < 256) {
            const float* h0k = sHG;
            const float* h1k = sHG + 192 * 8;
            int iR = eu * 8 + eb;
            int iZ = (64 + eu) * 8 + eb;
            int iN = (128 + eu) * 8 + eb;
            float hr = (h0k[iR] + h0k[iR + 4]) + (h1k[iR] + h1k[iR + 4]) + br_;
            float hz = (h0k[iZ] + h0k[iZ + 4]) + (h1k[iZ] + h1k[iZ + 4]) + bz_;
            float hn = (h0k[iN] + h0k[iN + 4]) + (h1k[iN] + h1k[iN + 4]) + bn_;
            float r = sigmoidf_(xr + hr);
            float z = sigmoidf_(xz + hz);
            float n = tanhf_(xn + r * hn);
            hnew = (1.0f - z) * n + z * hprev;
            hprev = hnew;
            __nv_bfloat16 hb = __float2bfloat16_rn(hnew);
            unsigned short hu = *(unsigned short*)&hb;
            __nv_bfloat16 lb = __float2bfloat16_rn(hnew - __bfloat162float(hb));
            unsigned short lu = *(unsigned short*)&lb;
            uint32_t pb = (uint32_t)((1 - p) * B_PHASE);
#pragma unroll
            for (uint32_t r = 0; r < 4; r++) {
                st_remote_b16(rH[r] + pb, hu);
                st_remote_b16(rL[r] + pb, lu);
            }
        }

        cluster_arrive_();   // release: publishes DSMEM h + frees sHG/B[p]

        // global stores off the critical path
        if (tid < 256) {
            if (layer == 0) {
                g_seq[((size_t)(b0 + eb) * T_LEN + t) * H_N + eug] = hnew;
            } else if (t == T_LEN - 1) {
                g_hlast[(b0 + eb) * H_N + eug] = hnew;
            }
        }
        p ^= 1;
    }
    cluster_wait_();
}

// ============================================================================
// Final FC
// ============================================================================
__global__ void fc_kernel(const float* __restrict__ Wfc,
                          const float* __restrict__ bfc,
                          float* __restrict__ out)
{
    __shared__ float sh[H_N];
    const int b = blockIdx.x, n = threadIdx.x;
    sh[n] = g_hlast[b * H_N + n];
    __syncthreads();
    const float* w = Wfc + (size_t)n * H_N;
    float acc = 0.0f;
#pragma unroll 4
    for (int k = 0; k < H_N; k++) acc += sh[k] * w[k];
    out[b * H_N + n] = sigmoidf_(acc + bfc[n]);
}

// ============================================================================
extern "C" void kernel_launch(void* const* d_in, const int* in_sizes, int n_in,
                              void* d_out, int out_size)
{
    const float* x   = (const float*)d_in[0];
    const float* Wih = (const float*)d_in[1];
    const float* Whh = (const float*)d_in[2];
    const float* bih = (const float*)d_in[3];
    const float* bhh = (const float*)d_in[4];
    const float* Wfc = (const float*)d_in[5];
    const float* bfc = (const float*)d_in[6];
    float* out = (float*)d_out;

    cudaFuncSetAttribute(gemm_mma_kernel, cudaFuncAttributeMaxDynamicSharedMemorySize, GT_SMEM);
    cudaFuncSetAttribute(gru_rec_tc_kernel, cudaFuncAttributeMaxDynamicSharedMemorySize, REC_SMEM);

    dim3 ggrid(12, T_LEN);

    // layer 0
    gemm_mma_kernel<<<ggrid, 256, GT_SMEM>>>(x, Wih, bih, 0);
    gru_rec_tc_kernel<<<128, 768, REC_SMEM>>>(Whh, bhh, 0);
    // layer 1
    gemm_mma_kernel<<<ggrid, 256, GT_SMEM>>>(nullptr, Wih + (size_t)G3 * H_N, bih + G3, 1);
    gru_rec_tc_kernel<<<128, 768, REC_SMEM>>>(Whh + (size_t)G3 * H_N, bhh + G3, 1);
    // head
    fc_kernel<<<B_N, H_N>>>(Wfc, bfc, out);
}

// round 17
// speedup vs baseline: 1.0861x; 1.0861x over previous
#include <cuda_runtime.h>
#include <cuda_bf16.h>
#include <cstdint>

#define T_LEN 1024
#define B_N   128
#define H_N   256
#define G3    768

typedef unsigned long long u64;

// ---------------- scratch (device globals; no allocations allowed) ----------
__device__ float g_xg[(size_t)T_LEN * B_N * G3];      // [t][b][768]
__device__ float g_seq[(size_t)B_N * T_LEN * H_N];    // [b][t][256] layer-1 output
__device__ float g_hlast[B_N * H_N];                  // layer-2 final hidden

// ---------------- helpers ---------------------------------------------------
__device__ __forceinline__ float sigmoidf_(float x) {
    return __fdividef(1.0f, 1.0f + __expf(-x));
}
__device__ __forceinline__ float tanhf_(float x) {
    float ax = fabsf(x);
    float e  = __expf(-2.0f * ax);
    float t  = __fdividef(1.0f - e, 1.0f + e);
    return copysignf(t, x);
}
__device__ __forceinline__ void cluster_arrive_() {
    asm volatile("barrier.cluster.arrive.aligned;" ::: "memory");
}
__device__ __forceinline__ void cluster_wait_() {
    asm volatile("barrier.cluster.wait.aligned;" ::: "memory");
}
__device__ __forceinline__ uint32_t smem_u32(const void* p) {
    return (uint32_t)__cvta_generic_to_shared(p);
}
__device__ __forceinline__ uint32_t mapa_(uint32_t laddr, uint32_t rank) {
    uint32_t raddr;
    asm volatile("mapa.shared::cluster.u32 %0, %1, %2;" : "=r"(raddr) : "r"(laddr), "r"(rank));
    return raddr;
}
__device__ __forceinline__ void mbar_init_(uint32_t addr, uint32_t cnt) {
    asm volatile("mbarrier.init.shared.b64 [%0], %1;" :: "r"(addr), "r"(cnt) : "memory");
}
__device__ __forceinline__ void mbar_arm_tx_(uint32_t addr, uint32_t tx) {
    asm volatile("mbarrier.arrive.expect_tx.shared.b64 _, [%0], %1;"
                 :: "r"(addr), "r"(tx) : "memory");
}
__device__ __forceinline__ void mbar_wait_(uint32_t addr, uint32_t parity) {
    asm volatile(
        "{\n\t.reg .pred P;\n\t"
        "W_%=:\n\t"
        "mbarrier.try_wait.parity.acquire.cluster.shared::cta.b64 P, [%0], %1, 0x989680;\n\t"
        "@P bra.uni D_%=;\n\t"
        "bra.uni W_%=;\n\t"
        "D_%=:\n\t}"
        :: "r"(addr), "r"(parity) : "memory");
}
// async remote smem store; completion (4 bytes) accounted on the TARGET CTA's mbarrier
__device__ __forceinline__ void st_async_b32(uint32_t raddr, uint32_t v, uint32_t rmbar) {
    asm volatile(
        "st.async.weak.shared::cluster.mbarrier::complete_tx::bytes.b32 [%0], %1, [%2];"
        :: "r"(raddr), "r"(v), "r"(rmbar) : "memory");
}

// ---- mma.sync / ldmatrix wrappers (sm_80-era PTX; valid on sm_100) ----
__device__ __forceinline__ void ldmx4_(uint32_t* r, uint32_t addr) {
    asm volatile("ldmatrix.sync.aligned.m8n8.x4.shared.b16 {%0,%1,%2,%3}, [%4];"
                 : "=r"(r[0]), "=r"(r[1]), "=r"(r[2]), "=r"(r[3]) : "r"(addr));
}
__device__ __forceinline__ void ldmx2_(uint32_t* r, uint32_t addr) {
    asm volatile("ldmatrix.sync.aligned.m8n8.x2.shared.b16 {%0,%1}, [%2];"
                 : "=r"(r[0]), "=r"(r[1]) : "r"(addr));
}
__device__ __forceinline__ void mma16816_(float* c, const uint32_t* a, const uint32_t* b) {
    asm volatile(
        "mma.sync.aligned.m16n8k16.row.col.f32.bf16.bf16.f32 "
        "{%0,%1,%2,%3}, {%4,%5,%6,%7}, {%8,%9}, {%0,%1,%2,%3};"
        : "+f"(c[0]), "+f"(c[1]), "+f"(c[2]), "+f"(c[3])
        : "r"(a[0]), "r"(a[1]), "r"(a[2]), "r"(a[3]), "r"(b[0]), "r"(b[1]));
}

// ============================================================================
// Input projection GEMM via mma.sync (unchanged — measured good)
// ============================================================================
#define GT_ST   264
#define OFF_BIAS 0
#define OFF_AHI  256
#define OFF_ALO  (OFF_AHI + 128 * GT_ST * 2)
#define OFF_BHI  (OFF_ALO + 128 * GT_ST * 2)
#define OFF_BLO  (OFF_BHI + 64 * GT_ST * 2)
#define GT_SMEM  (OFF_BLO + 64 * GT_ST * 2)

__global__ void __launch_bounds__(256, 1) gemm_mma_kernel(
    const float* __restrict__ Ax,
    const float* __restrict__ W,
    const float* __restrict__ bias,
    int use_gseq)
{
    extern __shared__ char smc[];
    const uint32_t sb = smem_u32(smc);
    float* sBias = (float*)(smc + OFF_BIAS);
    __nv_bfloat16* sAhi = (__nv_bfloat16*)(smc + OFF_AHI);
    __nv_bfloat16* sAlo = (__nv_bfloat16*)(smc + OFF_ALO);
    __nv_bfloat16* sBhi = (__nv_bfloat16*)(smc + OFF_BHI);
    __nv_bfloat16* sBlo = (__nv_bfloat16*)(smc + OFF_BLO);

    const float* A = use_gseq ? g_seq : Ax;

    const int tid = threadIdx.x;
    const int nt = blockIdx.x;
    const int t  = blockIdx.y;

    if (tid < 64) sBias[tid] = bias[nt * 64 + tid];

#pragma unroll
    for (int i = 0; i < 32; i++) {
        int ch  = i * 256 + tid;
        int row = ch >> 6;
        int c4  = (ch & 63) << 2;
        float4 v = *(const float4*)(A + ((size_t)row * T_LEN + t) * H_N + c4);
        __nv_bfloat16 h0 = __float2bfloat16_rn(v.x);
        __nv_bfloat16 h1 = __float2bfloat16_rn(v.y);
        __nv_bfloat16 h2 = __float2bfloat16_rn(v.z);
        __nv_bfloat16 h3 = __float2bfloat16_rn(v.w);
        __nv_bfloat16 l0 = __float2bfloat16_rn(v.x - __bfloat162float(h0));
        __nv_bfloat16 l1 = __float2bfloat16_rn(v.y - __bfloat162float(h1));
        __nv_bfloat16 l2 = __float2bfloat16_rn(v.z - __bfloat162float(h2));
        __nv_bfloat16 l3 = __float2bfloat16_rn(v.w - __bfloat162float(h3));
        int o = row * GT_ST + c4;
        *(__nv_bfloat162*)(sAhi + o)     = __nv_bfloat162(h0, h1);
        *(__nv_bfloat162*)(sAhi + o + 2) = __nv_bfloat162(h2, h3);
        *(__nv_bfloat162*)(sAlo + o)     = __nv_bfloat162(l0, l1);
        *(__nv_bfloat162*)(sAlo + o + 2) = __nv_bfloat162(l2, l3);
    }
#pragma unroll
    for (int i = 0; i < 16; i++) {
        int ch  = i * 256 + tid;
        int row = ch >> 6;
        int c4  = (ch & 63) << 2;
        float4 v = *(const float4*)(W + ((size_t)(nt * 64 + row)) * H_N + c4);
        __nv_bfloat16 h0 = __float2bfloat16_rn(v.x);
        __nv_bfloat16 h1 = __float2bfloat16_rn(v.y);
        __nv_bfloat16 h2 = __float2bfloat16_rn(v.z);
        __nv_bfloat16 h3 = __float2bfloat16_rn(v.w);
        __nv_bfloat16 l0 = __float2bfloat16_rn(v.x - __bfloat162float(h0));
        __nv_bfloat16 l1 = __float2bfloat16_rn(v.y - __bfloat162float(h1));
        __nv_bfloat16 l2 = __float2bfloat16_rn(v.z - __bfloat162float(h2));
        __nv_bfloat16 l3 = __float2bfloat16_rn(v.w - __bfloat162float(h3));
        int o = row * GT_ST + c4;
        *(__nv_bfloat162*)(sBhi + o)     = __nv_bfloat162(h0, h1);
        *(__nv_bfloat162*)(sBhi + o + 2) = __nv_bfloat162(h2, h3);
        *(__nv_bfloat162*)(sBlo + o)     = __nv_bfloat162(l0, l1);
        *(__nv_bfloat162*)(sBlo + o + 2) = __nv_bfloat162(l2, l3);
    }
    __syncthreads();

    const int wid = tid >> 5;
    const int l   = tid & 31;
    const int m0  = wid << 4;

    const uint32_t aHi = sb + OFF_AHI + ((m0 + (l & 15)) * GT_ST + ((l >> 4) << 3)) * 2;
    const uint32_t aLo = sb + OFF_ALO + ((m0 + (l & 15)) * GT_ST + ((l >> 4) << 3)) * 2;
    const uint32_t bHi = sb + OFF_BHI + (((l & 7)) * GT_ST + (((l >> 3) & 1) << 3)) * 2;
    const uint32_t bLo = sb + OFF_BLO + (((l & 7)) * GT_ST + (((l >> 3) & 1) << 3)) * 2;

    float acc[8][4];
#pragma unroll
    for (int j = 0; j < 8; j++)
#pragma unroll
        for (int i = 0; i < 4; i++) acc[j][i] = 0.0f;

#pragma unroll 2
    for (int ks = 0; ks < 16; ks++) {
        uint32_t ah[4], al[4];
        ldmx4_(ah, aHi + ks * 32);
        ldmx4_(al, aLo + ks * 32);
#pragma unroll
        for (int j = 0; j < 8; j++) {
            uint32_t bh[2], bl[2];
            ldmx2_(bh, bHi + j * (8 * GT_ST * 2) + ks * 32);
            ldmx2_(bl, bLo + j * (8 * GT_ST * 2) + ks * 32);
            mma16816_(acc[j], ah, bh);
            mma16816_(acc[j], ah, bl);
            mma16816_(acc[j], al, bh);
        }
    }

    {
        const int gp = l >> 2;
        const int tg = l & 3;
        float* dst0 = g_xg + ((size_t)t * B_N + m0 + gp) * G3 + nt * 64;
        float* dst1 = dst0 + 8 * G3;
#pragma unroll
        for (int j = 0; j < 8; j++) {
            int c = j * 8 + 2 * tg;
            float b0 = sBias[c], b1 = sBias[c + 1];
            *(float2*)(dst0 + c) = make_float2(acc[j][0] + b0, acc[j][1] + b1);
            *(float2*)(dst1 + c) = make_float2(acc[j][2] + b0, acc[j][3] + b1);
        }
    }
}

// ============================================================================
// GRU recurrence v13: R11 compute structure (packed-N MMA, 384 thr, 256
// owners) with the per-step cluster barrier replaced by TRANSACTION
// MBARRIERS + st.async:
//   full[0/1] (count=1, expect_tx=4096B = 4 CTAs x 1KB h hi/lo per rank).
//   Owners exchange hi/lo with shfl.xor(4) and issue 4 packed-b32 st.async
//   (visibility built into complete_tx; zero fences, zero arrives).
//   Buffer reuse safety by transitivity (full[p] flip requires every CTA's
//   previous-step stores, which follow that CTA's reads). sHG double-buffered.
// ============================================================================
#define R_ST      264
#define ROFF_ALO  0
#define ROFF_B    (192 * R_ST * 2)                  // [2 phases][8][264] bf16
#define ROFF_HG   (ROFF_B + 2 * 8 * R_ST * 2)       // [2][192][8] fp32
#define ROFF_MBAR (ROFF_HG + 2 * 192 * 8 * 4)       // full0, full1
#define REC_SMEM  (ROFF_MBAR + 16)
#define B_PHASE   (8 * R_ST * 2)
#define TX_BYTES  4096u

__global__ void __cluster_dims__(4, 1, 1) __launch_bounds__(384, 1)
gru_rec_tc_kernel(const float* __restrict__ Whh,   // this layer's [768][256]
                  const float* __restrict__ bhh,   // this layer's [768]
                  int layer)
{
    extern __shared__ char smc[];
    const uint32_t sb = smem_u32(smc);
    __nv_bfloat16* sAlo = (__nv_bfloat16*)(smc + ROFF_ALO);
    float* sHG = (float*)(smc + ROFF_HG);

    const int tid  = threadIdx.x;               // 0..383
    const int rank = blockIdx.x & 3;
    const int b0   = (blockIdx.x >> 2) * 4;

    const int wid = tid >> 5;                   // 0..11, m-tile index
    const int l   = tid & 31;

    // ---- mbarrier init + pre-arm (count=1: tid0's own arm arrival) ----
    if (tid == 0) {
        mbar_init_(sb + ROFF_MBAR, 1);
        mbar_init_(sb + ROFF_MBAR + 8, 1);
        mbar_arm_tx_(sb + ROFF_MBAR, TX_BYTES);
        mbar_arm_tx_(sb + ROFF_MBAR + 8, TX_BYTES);
    }

    // ---- zero combined B buffer (both phases; h=0 -> hi=lo=0) ----
    for (int i = tid; i < (2 * B_PHASE) / 4; i += 384)
        *(uint32_t*)(smc + ROFF_B + 4 * i) = 0u;

    // ---- fill sAlo with W_hi (bf16), ldmatrix A-hi frags to regs ----
    for (int idx = tid; idx < 192 * 128; idx += 384) {
        int row = idx >> 7;
        int kp  = idx & 127;
        int jg  = ((row >> 6) << 8) + (rank << 6) + (row & 63);
        float2 v = *(const float2*)(Whh + (size_t)jg * H_N + 2 * kp);
        __nv_bfloat162 hv(__float2bfloat16_rn(v.x), __float2bfloat16_rn(v.y));
        *(__nv_bfloat162*)(sAlo + row * R_ST + 2 * kp) = hv;
    }
    __syncthreads();

    uint32_t ahi[16][4];
    {
        uint32_t base = sb + ROFF_ALO + (uint32_t)((16 * wid + (l & 15)) * R_ST + ((l >> 4) << 3)) * 2;
#pragma unroll
        for (int ks = 0; ks < 16; ks++)
            ldmx4_(ahi[ks], base + ks * 32);
    }
    __syncthreads();

    // ---- overwrite sAlo with W_lo ----
    for (int idx = tid; idx < 192 * 128; idx += 384) {
        int row = idx >> 7;
        int kp  = idx & 127;
        int jg  = ((row >> 6) << 8) + (rank << 6) + (row & 63);
        float2 v = *(const float2*)(Whh + (size_t)jg * H_N + 2 * kp);
        __nv_bfloat16 h0 = __float2bfloat16_rn(v.x);
        __nv_bfloat16 h1 = __float2bfloat16_rn(v.y);
        __nv_bfloat162 lv(__float2bfloat16_rn(v.x - __bfloat162float(h0)),
                          __float2bfloat16_rn(v.y - __bfloat162float(h1)));
        *(__nv_bfloat162*)(sAlo + row * R_ST + 2 * kp) = lv;
    }

    // ---- owner assignment: tid<256, one (unit, batch) each ----
    const int eu  = tid >> 2;                   // 0..63 (valid tid<256)
    const int eb  = tid & 3;
    const int eug = (rank << 6) + (eu & 63);
    float br_ = 0.f, bz_ = 0.f, bn_ = 0.f;
    if (tid < 256) {
        br_ = bhh[eug]; bz_ = bhh[256 + eug]; bn_ = bhh[512 + eug];
    }
    float hprev = 0.0f;

    // ---- precomputed remote addresses: data slot (pair-packed) + mbarriers --
    uint32_t rD[4], rMB0[4], rMB1[4];
    {
        uint32_t offD;
        if ((eu & 1) == 0)       // even owner stores the hi-pair at (row eb, col eug)
            offD = (uint32_t)ROFF_B + (uint32_t)(eb * R_ST + eug) * 2;
        else                     // odd owner stores the lo-pair at (row eb+4, col eug-1)
            offD = (uint32_t)ROFF_B + (uint32_t)((eb + 4) * R_ST + (eug - 1)) * 2;
#pragma unroll
        for (uint32_t r = 0; r < 4; r++) {
            rD[r]   = mapa_(sb + offD, r);
            rMB0[r] = mapa_(sb + ROFF_MBAR, r);
            rMB1[r] = mapa_(sb + ROFF_MBAR + 8, r);
        }
    }

    // ldmatrix address bases (main loop)
    const uint32_t aloB = sb + ROFF_ALO + (uint32_t)((16 * wid + (l & 15)) * R_ST + ((l >> 4) << 3)) * 2;
    const uint32_t bOff = (uint32_t)((l & 7) * R_ST + (((l >> 3) & 1) << 3)) * 2;

    __syncthreads();
    cluster_arrive_();      // publish B zeros + mbarrier init/arm cluster-wide
    cluster_wait_();

    uint32_t fph0 = 0, fph1 = 0;

    int p = 0;
    for (int t = 0; t < T_LEN; t++) {
        const int w = 1 - p;

        // ---- xg prefetch (in flight during the wait) ----
        float xr = 0.f, xz = 0.f, xn = 0.f;
        if (tid < 256) {
            size_t xb = ((size_t)t * B_N + b0 + eb) * G3 + eug;
            xr = g_xg[xb]; xz = g_xg[xb + 256]; xn = g_xg[xb + 512];
        }

        // ---- wait h[p] delivered (tx-complete; acquire) ----
        if (t > 0) {
            uint32_t mb = sb + ROFF_MBAR + (uint32_t)p * 8;
            if (p) { mbar_wait_(mb, fph1); fph1 ^= 1; }
            else   { mbar_wait_(mb, fph0); fph0 ^= 1; }
            if (tid == 0) mbar_arm_tx_(mb, TX_BYTES);   // re-arm for next use
        }

        // ---- MMA phase: 2 passes over combined B (hi rows 0-3, lo rows 4-7)
        const uint32_t bB = sb + ROFF_B + p * B_PHASE + bOff;
        float cH[4] = {0.f, 0.f, 0.f, 0.f};
        float cL[4] = {0.f, 0.f, 0.f, 0.f};
#pragma unroll
        for (int ks = 0; ks < 16; ks++) {
            uint32_t bf[2], al[4];
            ldmx2_(bf, bB + ks * 32);
            ldmx4_(al, aloB + ks * 32);
            mma16816_(cH, ahi[ks], bf);
            mma16816_(cL, al, bf);
        }
        float c0[4];
#pragma unroll
        for (int i = 0; i < 4; i++) c0[i] = cH[i] + cL[i];

        // ---- stage D frags -> sHG[p][row][8] (double-buffered) ----
        {
            float* hg = sHG + p * (192 * 8);
            int r0 = 16 * wid + (l >> 2);
            *(float2*)(hg + r0 * 8 + 2 * (l & 3))       = make_float2(c0[0], c0[1]);
            *(float2*)(hg + (r0 + 8) * 8 + 2 * (l & 3)) = make_float2(c0[2], c0[3]);
        }
        __syncthreads();

        // ---- elementwise + paired st.async broadcast ----
        float hnew = 0.f;
        if (tid < 256) {
            const float* hg = sHG + p * (192 * 8);
            float hr = hg[eu * 8 + eb]         + hg[eu * 8 + 4 + eb]         + br_;
            float hz = hg[(64 + eu) * 8 + eb]  + hg[(64 + eu) * 8 + 4 + eb]  + bz_;
            float hn = hg[(128 + eu) * 8 + eb] + hg[(128 + eu) * 8 + 4 + eb] + bn_;
            float r = sigmoidf_(xr + hr);
            float z = sigmoidf_(xz + hz);
            float n = tanhf_(xn + r * hn);
            hnew = (1.0f - z) * n + z * hprev;
            hprev = hnew;

            __nv_bfloat16 hb = __float2bfloat16_rn(hnew);
            __nv_bfloat16 lb = __float2bfloat16_rn(hnew - __bfloat162float(hb));
            uint32_t mine = (uint32_t)(*(unsigned short*)&hb)
                          | ((uint32_t)(*(unsigned short*)&lb) << 16);
            uint32_t other = __shfl_xor_sync(0xffffffffu, mine, 4);
            uint32_t val;
            if ((eu & 1) == 0)   // hi-pair: low = my hi, high = partner's hi
                val = (mine & 0xffffu) | (other << 16);
            else                  // lo-pair: low = partner's lo, high = my lo
                val = (other >> 16) | (mine & 0xffff0000u);

            uint32_t pb = (uint32_t)w * B_PHASE;
            if (w) {
#pragma unroll
                for (uint32_t r = 0; r < 4; r++) st_async_b32(rD[r] + pb, val, rMB1[r]);
            } else {
#pragma unroll
                for (uint32_t r = 0; r < 4; r++) st_async_b32(rD[r] + pb, val, rMB0[r]);
            }

            // global stores (not on the cluster critical path)
            if (layer == 0) {
                g_seq[((size_t)(b0 + eb) * T_LEN + t) * H_N + eug] = hnew;
            } else if (t == T_LEN - 1) {
                g_hlast[(b0 + eb) * H_N + eug] = hnew;
            }
        }
        p ^= 1;
    }
    cluster_arrive_();   // don't exit while peers' st.async to our smem in flight
    cluster_wait_();
}

// ============================================================================
// Final FC
// ============================================================================
__global__ void fc_kernel(const float* __restrict__ Wfc,
                          const float* __restrict__ bfc,
                          float* __restrict__ out)
{
    __shared__ float sh[H_N];
    const int b = blockIdx.x, n = threadIdx.x;
    sh[n] = g_hlast[b * H_N + n];
    __syncthreads();
    const float* w = Wfc + (size_t)n * H_N;
    float acc = 0.0f;
#pragma unroll 4
    for (int k = 0; k < H_N; k++) acc += sh[k] * w[k];
    out[b * H_N + n] = sigmoidf_(acc + bfc[n]);
}

// ============================================================================
extern "C" void kernel_launch(void* const* d_in, const int* in_sizes, int n_in,
                              void* d_out, int out_size)
{
    const float* x   = (const float*)d_in[0];
    const float* Wih = (const float*)d_in[1];
    const float* Whh = (const float*)d_in[2];
    const float* bih = (const float*)d_in[3];
    const float* bhh = (const float*)d_in[4];
    const float* Wfc = (const float*)d_in[5];
    const float* bfc = (const float*)d_in[6];
    float* out = (float*)d_out;

    cudaFuncSetAttribute(gemm_mma_kernel, cudaFuncAttributeMaxDynamicSharedMemorySize, GT_SMEM);
    cudaFuncSetAttribute(gru_rec_tc_kernel, cudaFuncAttributeMaxDynamicSharedMemorySize, REC_SMEM);

    dim3 ggrid(12, T_LEN);

    // layer 0
    gemm_mma_kernel<<<ggrid, 256, GT_SMEM>>>(x, Wih, bih, 0);
    gru_rec_tc_kernel<<<128, 384, REC_SMEM>>>(Whh, bhh, 0);
    // layer 1
    gemm_mma_kernel<<<ggrid, 256, GT_SMEM>>>(nullptr, Wih + (size_t)G3 * H_N, bih + G3, 1);
    gru_rec_tc_kernel<<<128, 384, REC_SMEM>>>(Whh + (size_t)G3 * H_N, bhh + G3, 1);
    // head
    fc_kernel<<<B_N, H_N>>>(Wfc, bfc, out);
}